// round 16
// baseline (speedup 1.0000x reference)
#include <cuda_runtime.h>
#include <stdint.h>

#define BB 8
#define LL 4096
#define KK 576
#define DD 4096
#define IMG_TOK 32000
#define IGNORE (-100.0f)

#define NCOPY (BB * LL)                    // 32768 copy blocks, 1 row each
#define CHUNK 1024                         // tokens per scan block
#define NSCANB (BB * LL / CHUNK)           // 32 scan blocks (launched FIRST)

// ---------------------------------------------------------------------------
// One kernel, all blocks fully independent (no inter-block sync, no state).
//  bid < NSCANB : one 1024-token chunk of the small outputs (wave 1 -> hidden)
//                 (uses 128 threads x 8 tokens each)
//  bid >= NSCANB: stream ONE embedding row with 128 threads x 8 float4
//                 (deeper per-thread MLP). Image-token prefix count runs
//                 with trip-count 0 for text rows (branchless gating).
// ---------------------------------------------------------------------------
__global__ __launch_bounds__(128) void fused_kernel(
    const int*    __restrict__ input_ids,
    const int*    __restrict__ attention_mask,
    const int*    __restrict__ labels,
    const float4* __restrict__ feat,       // (B,K,D)
    const float4* __restrict__ emb,        // (B,L,D)
    float4*       __restrict__ out,        // (B,L,D)
    float*        __restrict__ out_tail)   // out + B*L*D
{
    const int bid  = blockIdx.x;
    const int tid  = threadIdx.x;          // 0..127
    const int lane = tid & 31;
    const int wid  = tid >> 5;             // 4 warps

    if (bid >= NSCANB) {
        // ================= COPY PATH (1 row, 128 threads) =================
        const int row = bid - NSCANB;            // 0 .. B*L-1
        const int b   = row >> 12;               // batch row
        const int l0  = row & (LL - 1);          // position within the row
        const int* ids_row = input_ids + b * LL;

        const int my_id = ids_row[l0];           // uniform broadcast load
        // trip count is 0 for text rows -> loop vanishes, no branch structure
        const int need = (my_id == IMG_TOK) ? l0 : 0;

        int local = 0;
        for (int i0 = tid * 4; i0 < need; i0 += 512) {
            int4 v = *(const int4*)(ids_row + i0);      // aligned, in-bounds
            local += (v.x == IMG_TOK && i0 + 0 < need)
                   + (v.y == IMG_TOK && i0 + 1 < need)
                   + (v.z == IMG_TOK && i0 + 2 < need)
                   + (v.w == IMG_TOK && i0 + 3 < need);
        }
        #pragma unroll
        for (int o = 16; o; o >>= 1) local += __shfl_down_sync(~0u, local, o);

        __shared__ int s_warp[4];
        if (lane == 0) s_warp[wid] = local;
        __syncthreads();
        int rank = s_warp[0] + s_warp[1] + s_warp[2] + s_warp[3];

        const int D4 = DD / 4;                   // 1024 float4 per row
        float4* dst = out + (size_t)row * D4;

        if (my_id == IMG_TOK && rank >= KK) {
            // extra placeholder -> zeros
            float4 z = make_float4(0.f, 0.f, 0.f, 0.f);
            #pragma unroll
            for (int i = 0; i < 8; i++) dst[i * 128 + tid] = z;
        } else {
            const float4* src = (my_id == IMG_TOK)
                ? feat + ((size_t)b * KK + rank) * D4
                : emb  + (size_t)row * D4;
            float4 r0 = src[0 * 128 + tid];      // 8 independent LDG.128
            float4 r1 = src[1 * 128 + tid];
            float4 r2 = src[2 * 128 + tid];
            float4 r3 = src[3 * 128 + tid];
            float4 r4 = src[4 * 128 + tid];
            float4 r5 = src[5 * 128 + tid];
            float4 r6 = src[6 * 128 + tid];
            float4 r7 = src[7 * 128 + tid];
            dst[0 * 128 + tid] = r0;
            dst[1 * 128 + tid] = r1;
            dst[2 * 128 + tid] = r2;
            dst[3 * 128 + tid] = r3;
            dst[4 * 128 + tid] = r4;
            dst[5 * 128 + tid] = r5;
            dst[6 * 128 + tid] = r6;
            dst[7 * 128 + tid] = r7;
        }
    } else {
        // ================= SCAN PATH (one 1024-token chunk) ===============
        // 128 threads x 8 tokens each
        const int sb    = bid;                    // 0..31
        const int b     = sb >> 2;                // batch row
        const int chunk = sb & 3;                 // which quarter of the row
        const int cs    = chunk * CHUNK;          // chunk start (local)
        const int* ids_row = input_ids + b * LL;
        const int* am_row  = attention_mask + b * LL;

        // ---- redundant prefix over [0, cs): img count + non-img attn sum --
        int img_pre = 0, amn_pre = 0;
        for (int i = tid * 4; i < cs; i += 512) {
            int4 v = *(const int4*)(ids_row + i);
            int4 a = *(const int4*)(am_row + i);
            img_pre += (v.x == IMG_TOK) + (v.y == IMG_TOK)
                     + (v.z == IMG_TOK) + (v.w == IMG_TOK);
            amn_pre += (v.x == IMG_TOK ? 0 : a.x) + (v.y == IMG_TOK ? 0 : a.y)
                     + (v.z == IMG_TOK ? 0 : a.z) + (v.w == IMG_TOK ? 0 : a.w);
        }
        #pragma unroll
        for (int o = 16; o; o >>= 1) {
            img_pre += __shfl_down_sync(~0u, img_pre, o);
            amn_pre += __shfl_down_sync(~0u, amn_pre, o);
        }
        __shared__ int s_img, s_amn;
        if (tid == 0) { s_img = 0; s_amn = 0; }
        __syncthreads();
        if (lane == 0) {
            if (img_pre) atomicAdd(&s_img, img_pre);
            if (amn_pre) atomicAdd(&s_amn, amn_pre);
        }
        __syncthreads();
        const int IMG_PRE  = s_img;
        // attn prefix: writes before cs = min(img_pre, K); plus text attn sum
        const int ATTN_PRE = (IMG_PRE < KK ? IMG_PRE : KK) + s_amn;

        // ---- chunk body: 128 threads x 8 tokens ----
        const int base = b * LL + cs + tid * 8;   // global token index
        int4 ida = *(const int4*)(input_ids + base);
        int4 idb = *(const int4*)(input_ids + base + 4);
        int im[8] = { ida.x == IMG_TOK, ida.y == IMG_TOK, ida.z == IMG_TOK, ida.w == IMG_TOK,
                      idb.x == IMG_TOK, idb.y == IMG_TOK, idb.z == IMG_TOK, idb.w == IMG_TOK };
        int local = 0;
        #pragma unroll
        for (int i = 0; i < 8; i++) local += im[i];

        __shared__ int warp_sums[4];

        // block scan #1: in-chunk image-token ranks
        int v = local;
        #pragma unroll
        for (int o = 1; o < 32; o <<= 1) { int n = __shfl_up_sync(~0u, v, o); if (lane >= o) v += n; }
        if (lane == 31) warp_sums[wid] = v;
        __syncthreads();
        if (wid == 0 && lane < 4) {
            int s = warp_sums[lane];
            #pragma unroll
            for (int o = 1; o < 4; o <<= 1) {
                int n = __shfl_up_sync(0xfu, s, o); if (lane >= o) s += n;
            }
            warp_sums[lane] = s;
        }
        __syncthreads();
        int rank0 = IMG_PRE + (v - local) + (wid > 0 ? warp_sums[wid - 1] : 0);

        int4 ama = *(const int4*)(attention_mask + base);
        int4 amb = *(const int4*)(attention_mask + base + 4);
        int4 lba = *(const int4*)(labels + base);
        int4 lbb = *(const int4*)(labels + base + 4);
        int am[8] = { ama.x, ama.y, ama.z, ama.w, amb.x, amb.y, amb.z, amb.w };
        int lb[8] = { lba.x, lba.y, lba.z, lba.w, lbb.x, lbb.y, lbb.z, lbb.w };

        int   fattn[8];
        float flab[8], fmask[8];
        int run = rank0;
        #pragma unroll
        for (int i = 0; i < 8; i++) {
            if (im[i]) {
                int wr = (run < KK); run++;
                fattn[i] = wr;
                fmask[i] = wr ? 1.0f : 0.0f;     // extra -> id PAD(0)
                flab[i]  = IGNORE;
            } else {
                fattn[i] = am[i];
                fmask[i] = 0.0f;
                flab[i]  = (float)lb[i];
            }
        }

        __syncthreads();   // reuse warp_sums
        // block scan #2: in-chunk attn cumsum -> position_ids
        int local2 = 0;
        #pragma unroll
        for (int i = 0; i < 8; i++) local2 += fattn[i];
        int v2 = local2;
        #pragma unroll
        for (int o = 1; o < 32; o <<= 1) { int n = __shfl_up_sync(~0u, v2, o); if (lane >= o) v2 += n; }
        if (lane == 31) warp_sums[wid] = v2;
        __syncthreads();
        if (wid == 0 && lane < 4) {
            int s = warp_sums[lane];
            #pragma unroll
            for (int o = 1; o < 4; o <<= 1) {
                int n = __shfl_up_sync(0xfu, s, o); if (lane >= o) s += n;
            }
            warp_sums[lane] = s;
        }
        __syncthreads();
        int csum = ATTN_PRE + (v2 - local2) + (wid > 0 ? warp_sums[wid - 1] : 0);

        float fpos[8];
        #pragma unroll
        for (int i = 0; i < 8; i++) {
            csum += fattn[i];
            int p = csum - 1;
            fpos[i] = (float)(p < 0 ? 0 : p);
        }

        const int NTOK = BB * LL;
        #pragma unroll
        for (int h = 0; h < 2; h++) {
            int o = h * 4;
            *(float4*)(out_tail + 0 * NTOK + base + o) =
                make_float4((float)fattn[o], (float)fattn[o+1], (float)fattn[o+2], (float)fattn[o+3]);
            *(float4*)(out_tail + 1 * NTOK + base + o) =
                make_float4(flab[o], flab[o+1], flab[o+2], flab[o+3]);
            *(float4*)(out_tail + 2 * NTOK + base + o) =
                make_float4(fpos[o], fpos[o+1], fpos[o+2], fpos[o+3]);
            *(float4*)(out_tail + 3 * NTOK + base + o) =
                make_float4(fmask[o], fmask[o+1], fmask[o+2], fmask[o+3]);
        }
    }
}

// ---------------------------------------------------------------------------
extern "C" void kernel_launch(void* const* d_in, const int* in_sizes, int n_in,
                              void* d_out, int out_size)
{
    const float* image_features = (const float*)d_in[0];   // (B,K,D) f32
    const float* inputs_embeds  = (const float*)d_in[1];   // (B,L,D) f32
    const int*   input_ids      = (const int*)d_in[2];     // (B,L) i32
    const int*   attention_mask = (const int*)d_in[3];     // (B,L) i32
    const int*   labels         = (const int*)d_in[4];     // (B,L) i32

    float* out = (float*)d_out;
    float* out_tail = out + (size_t)BB * LL * DD;

    fused_kernel<<<NSCANB + NCOPY, 128>>>(
        input_ids, attention_mask, labels,
        (const float4*)image_features,
        (const float4*)inputs_embeds,
        (float4*)out, out_tail);
}

// round 17
// speedup vs baseline: 1.0065x; 1.0065x over previous
#include <cuda_runtime.h>
#include <stdint.h>

#define BB 8
#define LL 4096
#define KK 576
#define DD 4096
#define IMG_TOK 32000
#define IGNORE (-100.0f)

#define NCOPY (BB * LL)                    // 32768 copy blocks, 1 row each
#define CHUNK 1024                         // tokens per scan block
#define NSCANB (BB * LL / CHUNK)           // 32 scan blocks (launched FIRST)

// ---------------------------------------------------------------------------
// One kernel, all blocks fully independent (no inter-block sync, no state).
//  bid < NSCANB : one 1024-token chunk of the small outputs (wave 1 -> hidden)
//  bid >= NSCANB: stream ONE embedding row. Image-token prefix count runs
//                 with trip-count 0 for text rows (branchless gating).
// Converged configuration (R15): 256 thr/block, 4 float4/thread, coherent
// loads, no cache hints. Measured 85.8% DRAM / 6.8 TB/s — the HBM mixed
// read/write ceiling for this traffic.
// ---------------------------------------------------------------------------
__global__ __launch_bounds__(256) void fused_kernel(
    const int*    __restrict__ input_ids,
    const int*    __restrict__ attention_mask,
    const int*    __restrict__ labels,
    const float4* __restrict__ feat,       // (B,K,D)
    const float4* __restrict__ emb,        // (B,L,D)
    float4*       __restrict__ out,        // (B,L,D)
    float*        __restrict__ out_tail)   // out + B*L*D
{
    const int bid  = blockIdx.x;
    const int tid  = threadIdx.x;          // 0..255
    const int lane = tid & 31;
    const int wid  = tid >> 5;             // 8 warps

    if (bid >= NSCANB) {
        // ================= COPY PATH (1 row, 256 threads) =================
        const int row = bid - NSCANB;            // 0 .. B*L-1
        const int b   = row >> 12;               // batch row
        const int l0  = row & (LL - 1);          // position within the row
        const int* ids_row = input_ids + b * LL;

        const int my_id = ids_row[l0];           // uniform broadcast load
        // trip count is 0 for text rows -> loop vanishes, no branch structure
        const int need = (my_id == IMG_TOK) ? l0 : 0;

        int local = 0;
        for (int i0 = tid * 4; i0 < need; i0 += 1024) {
            int4 v = *(const int4*)(ids_row + i0);      // aligned, in-bounds
            local += (v.x == IMG_TOK && i0 + 0 < need)
                   + (v.y == IMG_TOK && i0 + 1 < need)
                   + (v.z == IMG_TOK && i0 + 2 < need)
                   + (v.w == IMG_TOK && i0 + 3 < need);
        }
        #pragma unroll
        for (int o = 16; o; o >>= 1) local += __shfl_down_sync(~0u, local, o);

        __shared__ int s_warp[8];
        if (lane == 0) s_warp[wid] = local;
        __syncthreads();
        int rank = s_warp[0] + s_warp[1] + s_warp[2] + s_warp[3]
                 + s_warp[4] + s_warp[5] + s_warp[6] + s_warp[7];

        const int D4 = DD / 4;                   // 1024 float4 per row
        float4* dst = out + (size_t)row * D4;

        if (my_id == IMG_TOK && rank >= KK) {
            // extra placeholder -> zeros
            float4 z = make_float4(0.f, 0.f, 0.f, 0.f);
            #pragma unroll
            for (int i = 0; i < 4; i++) dst[i * 256 + tid] = z;
        } else {
            const float4* src = (my_id == IMG_TOK)
                ? feat + ((size_t)b * KK + rank) * D4
                : emb  + (size_t)row * D4;
            float4 r0 = src[0 * 256 + tid];
            float4 r1 = src[1 * 256 + tid];
            float4 r2 = src[2 * 256 + tid];
            float4 r3 = src[3 * 256 + tid];
            dst[0 * 256 + tid] = r0;
            dst[1 * 256 + tid] = r1;
            dst[2 * 256 + tid] = r2;
            dst[3 * 256 + tid] = r3;
        }
    } else {
        // ================= SCAN PATH (one 1024-token chunk) ===============
        const int sb    = bid;                    // 0..31
        const int b     = sb >> 2;                // batch row
        const int chunk = sb & 3;                 // which quarter of the row
        const int cs    = chunk * CHUNK;          // chunk start (local)
        const int* ids_row = input_ids + b * LL;
        const int* am_row  = attention_mask + b * LL;

        // ---- redundant prefix over [0, cs): img count + non-img attn sum --
        int img_pre = 0, amn_pre = 0;
        for (int k = 0; k < chunk; k++) {
            int i = (k * 256 + tid) * 4;
            int4 v = *(const int4*)(ids_row + i);
            int4 a = *(const int4*)(am_row + i);
            img_pre += (v.x == IMG_TOK) + (v.y == IMG_TOK)
                     + (v.z == IMG_TOK) + (v.w == IMG_TOK);
            amn_pre += (v.x == IMG_TOK ? 0 : a.x) + (v.y == IMG_TOK ? 0 : a.y)
                     + (v.z == IMG_TOK ? 0 : a.z) + (v.w == IMG_TOK ? 0 : a.w);
        }
        #pragma unroll
        for (int o = 16; o; o >>= 1) {
            img_pre += __shfl_down_sync(~0u, img_pre, o);
            amn_pre += __shfl_down_sync(~0u, amn_pre, o);
        }
        __shared__ int s_img, s_amn;
        if (tid == 0) { s_img = 0; s_amn = 0; }
        __syncthreads();
        if (lane == 0) {
            if (img_pre) atomicAdd(&s_img, img_pre);
            if (amn_pre) atomicAdd(&s_amn, amn_pre);
        }
        __syncthreads();
        const int IMG_PRE  = s_img;
        // attn prefix: writes before cs = min(img_pre, K); plus text attn sum
        const int ATTN_PRE = (IMG_PRE < KK ? IMG_PRE : KK) + s_amn;

        // ---- chunk body: 256 threads x 4 tokens ----
        const int base = b * LL + cs + tid * 4;   // global token index
        int4 id4 = *(const int4*)(input_ids + base);
        int im[4] = { id4.x == IMG_TOK, id4.y == IMG_TOK,
                      id4.z == IMG_TOK, id4.w == IMG_TOK };
        int local = im[0] + im[1] + im[2] + im[3];

        __shared__ int warp_sums[8];

        // block scan #1: in-chunk image-token ranks
        int v = local;
        #pragma unroll
        for (int o = 1; o < 32; o <<= 1) { int n = __shfl_up_sync(~0u, v, o); if (lane >= o) v += n; }
        if (lane == 31) warp_sums[wid] = v;
        __syncthreads();
        if (wid == 0 && lane < 8) {
            int s = warp_sums[lane];
            #pragma unroll
            for (int o = 1; o < 8; o <<= 1) {
                int n = __shfl_up_sync(0xffu, s, o); if (lane >= o) s += n;
            }
            warp_sums[lane] = s;
        }
        __syncthreads();
        int rank0 = IMG_PRE + (v - local) + (wid > 0 ? warp_sums[wid - 1] : 0);

        int4 am4 = *(const int4*)(attention_mask + base);
        int4 lb4 = *(const int4*)(labels + base);
        int am[4] = { am4.x, am4.y, am4.z, am4.w };
        int lb[4] = { lb4.x, lb4.y, lb4.z, lb4.w };

        int   fattn[4];
        float flab[4], fmask[4];
        int run = rank0;
        #pragma unroll
        for (int i = 0; i < 4; i++) {
            if (im[i]) {
                int wr = (run < KK); run++;
                fattn[i] = wr;
                fmask[i] = wr ? 1.0f : 0.0f;     // extra -> id PAD(0)
                flab[i]  = IGNORE;
            } else {
                fattn[i] = am[i];
                fmask[i] = 0.0f;
                flab[i]  = (float)lb[i];
            }
        }

        __syncthreads();   // reuse warp_sums
        // block scan #2: in-chunk attn cumsum -> position_ids
        int local2 = fattn[0] + fattn[1] + fattn[2] + fattn[3];
        int v2 = local2;
        #pragma unroll
        for (int o = 1; o < 32; o <<= 1) { int n = __shfl_up_sync(~0u, v2, o); if (lane >= o) v2 += n; }
        if (lane == 31) warp_sums[wid] = v2;
        __syncthreads();
        if (wid == 0 && lane < 8) {
            int s = warp_sums[lane];
            #pragma unroll
            for (int o = 1; o < 8; o <<= 1) {
                int n = __shfl_up_sync(0xffu, s, o); if (lane >= o) s += n;
            }
            warp_sums[lane] = s;
        }
        __syncthreads();
        int csum = ATTN_PRE + (v2 - local2) + (wid > 0 ? warp_sums[wid - 1] : 0);

        float fpos[4];
        #pragma unroll
        for (int i = 0; i < 4; i++) {
            csum += fattn[i];
            int p = csum - 1;
            fpos[i] = (float)(p < 0 ? 0 : p);
        }

        const int NTOK = BB * LL;
        *(float4*)(out_tail + 0 * NTOK + base) =
            make_float4((float)fattn[0], (float)fattn[1], (float)fattn[2], (float)fattn[3]);
        *(float4*)(out_tail + 1 * NTOK + base) = make_float4(flab[0], flab[1], flab[2], flab[3]);
        *(float4*)(out_tail + 2 * NTOK + base) = make_float4(fpos[0], fpos[1], fpos[2], fpos[3]);
        *(float4*)(out_tail + 3 * NTOK + base) = make_float4(fmask[0], fmask[1], fmask[2], fmask[3]);
    }
}

// ---------------------------------------------------------------------------
extern "C" void kernel_launch(void* const* d_in, const int* in_sizes, int n_in,
                              void* d_out, int out_size)
{
    const float* image_features = (const float*)d_in[0];   // (B,K,D) f32
    const float* inputs_embeds  = (const float*)d_in[1];   // (B,L,D) f32
    const int*   input_ids      = (const int*)d_in[2];     // (B,L) i32
    const int*   attention_mask = (const int*)d_in[3];     // (B,L) i32
    const int*   labels         = (const int*)d_in[4];     // (B,L) i32

    float* out = (float*)d_out;
    float* out_tail = out + (size_t)BB * LL * DD;

    fused_kernel<<<NSCANB + NCOPY, 256>>>(
        input_ids, attention_mask, labels,
        (const float4*)image_features,
        (const float4*)inputs_embeds,
        (float4*)out, out_tail);
}